// round 2
// baseline (speedup 1.0000x reference)
#include <cuda_runtime.h>

#define NB 65536
#define KK 20

// Scratch (allocation-free rule: __device__ globals)
__device__ float g_X[(size_t)NB * 448];   // assembled input  [B,448]
__device__ float g_H1[(size_t)NB * 256];  // layer-1 output   [B,256]

// ---------------------------------------------------------------------------
// Kernel 1: assemble X = [emb_user | emb_item | mean_prior | mean_target | mean_itemk]
// One block per row b, 5 warps: w0=user gather, w1=item gather, w2..4 = masked means.
// Mean warps: lanes 0-15 handle even k, 16-31 odd k (doubles MLP), float4 over dims.
// ---------------------------------------------------------------------------
__global__ __launch_bounds__(160) void k_assemble(
    const int* __restrict__ user, const int* __restrict__ item,
    const int* __restrict__ pk, const int* __restrict__ tk, const int* __restrict__ ik,
    const int* __restrict__ vp, const int* __restrict__ vt, const int* __restrict__ vi,
    const float* __restrict__ eu, const float* __restrict__ ei, const float* __restrict__ ek)
{
    int b = blockIdx.x;
    int w = threadIdx.x >> 5, lane = threadIdx.x & 31;
    float4* Xrow = (float4*)(g_X + (size_t)b * 448);

    if (w == 0) {
        const float4* src = (const float4*)(eu + (size_t)user[b] * 128);
        Xrow[lane] = src[lane];
    } else if (w == 1) {
        const float4* src = (const float4*)(ei + (size_t)item[b] * 128);
        Xrow[32 + lane] = src[lane];
    } else {
        const int* idx; int valid; int off4;
        if (w == 2)      { idx = pk; valid = vp[b]; off4 = 64; }
        else if (w == 3) { idx = tk; valid = vt[b]; off4 = 80; }
        else             { idx = ik; valid = vi[b]; off4 = 96; }
        int d = lane & 15, ko = lane >> 4;
        float4 acc = make_float4(0.f, 0.f, 0.f, 0.f);
        for (int k = ko; k < valid; k += 2) {
            int r = idx[b * KK + k];
            float4 v = ((const float4*)(ek + (size_t)r * 64))[d];
            acc.x += v.x; acc.y += v.y; acc.z += v.z; acc.w += v.w;
        }
        acc.x += __shfl_xor_sync(0xffffffffu, acc.x, 16);
        acc.y += __shfl_xor_sync(0xffffffffu, acc.y, 16);
        acc.z += __shfl_xor_sync(0xffffffffu, acc.z, 16);
        acc.w += __shfl_xor_sync(0xffffffffu, acc.w, 16);
        if (lane < 16) {
            float s = (valid > 0) ? (1.f / (float)valid) : 0.f;
            acc.x *= s; acc.y *= s; acc.z *= s; acc.w *= s;
            Xrow[off4 + d] = acc;
        }
    }
}

// ---------------------------------------------------------------------------
// Kernel 2: H1 = relu(X @ W1 + b1)    [65536,448] x [448,256]
// 128x128x16 tiled SGEMM, double-buffered smem, 256 threads, 8x8 micro-tile.
// ---------------------------------------------------------------------------
__global__ __launch_bounds__(256) void k_gemm1(const float* __restrict__ W1,
                                               const float* __restrict__ b1)
{
    __shared__ float As[2][16][128];   // [k][m] (A stored transposed)
    __shared__ float Bs[2][16][128];   // [k][n]
    const int tid = threadIdx.x;
    const int rowBase = blockIdx.x * 128;
    const int colBase = blockIdx.y * 128;
    const int tr = tid >> 4, tc = tid & 15;

    const int ar0 = tid >> 2,          ac0 = (tid & 3) * 4;
    const int ar1 = (tid + 256) >> 2,  ac1 = ((tid + 256) & 3) * 4;
    const int br0 = tid >> 5,          bc0 = (tid & 31) * 4;
    const int br1 = (tid + 256) >> 5,  bc1 = ((tid + 256) & 31) * 4;

    const float* Xp = g_X + (size_t)rowBase * 448;

    float acc[8][8];
    #pragma unroll
    for (int i = 0; i < 8; i++)
        #pragma unroll
        for (int j = 0; j < 8; j++) acc[i][j] = 0.f;

    float4 va0, va1, vb0, vb1;
    va0 = *(const float4*)(Xp + (size_t)ar0 * 448 + ac0);
    va1 = *(const float4*)(Xp + (size_t)ar1 * 448 + ac1);
    vb0 = *(const float4*)(W1 + (size_t)br0 * 256 + colBase + bc0);
    vb1 = *(const float4*)(W1 + (size_t)br1 * 256 + colBase + bc1);
    As[0][ac0 + 0][ar0] = va0.x; As[0][ac0 + 1][ar0] = va0.y;
    As[0][ac0 + 2][ar0] = va0.z; As[0][ac0 + 3][ar0] = va0.w;
    As[0][ac1 + 0][ar1] = va1.x; As[0][ac1 + 1][ar1] = va1.y;
    As[0][ac1 + 2][ar1] = va1.z; As[0][ac1 + 3][ar1] = va1.w;
    *(float4*)&Bs[0][br0][bc0] = vb0;
    *(float4*)&Bs[0][br1][bc1] = vb1;
    __syncthreads();

    int buf = 0;
    const int NT = 448 / 16;  // 28
    for (int kt = 0; kt < NT; kt++) {
        const int kNext = (kt + 1) * 16;
        if (kt + 1 < NT) {
            va0 = *(const float4*)(Xp + (size_t)ar0 * 448 + kNext + ac0);
            va1 = *(const float4*)(Xp + (size_t)ar1 * 448 + kNext + ac1);
            vb0 = *(const float4*)(W1 + (size_t)(kNext + br0) * 256 + colBase + bc0);
            vb1 = *(const float4*)(W1 + (size_t)(kNext + br1) * 256 + colBase + bc1);
        }
        #pragma unroll
        for (int k = 0; k < 16; k++) {
            float4 fa0 = *(const float4*)&As[buf][k][tr * 8];
            float4 fa1 = *(const float4*)&As[buf][k][tr * 8 + 4];
            float4 fb0 = *(const float4*)&Bs[buf][k][tc * 8];
            float4 fb1 = *(const float4*)&Bs[buf][k][tc * 8 + 4];
            float a[8] = {fa0.x, fa0.y, fa0.z, fa0.w, fa1.x, fa1.y, fa1.z, fa1.w};
            float bb[8] = {fb0.x, fb0.y, fb0.z, fb0.w, fb1.x, fb1.y, fb1.z, fb1.w};
            #pragma unroll
            for (int i = 0; i < 8; i++)
                #pragma unroll
                for (int j = 0; j < 8; j++)
                    acc[i][j] = fmaf(a[i], bb[j], acc[i][j]);
        }
        if (kt + 1 < NT) {
            int nb = buf ^ 1;
            As[nb][ac0 + 0][ar0] = va0.x; As[nb][ac0 + 1][ar0] = va0.y;
            As[nb][ac0 + 2][ar0] = va0.z; As[nb][ac0 + 3][ar0] = va0.w;
            As[nb][ac1 + 0][ar1] = va1.x; As[nb][ac1 + 1][ar1] = va1.y;
            As[nb][ac1 + 2][ar1] = va1.z; As[nb][ac1 + 3][ar1] = va1.w;
            *(float4*)&Bs[nb][br0][bc0] = vb0;
            *(float4*)&Bs[nb][br1][bc1] = vb1;
            __syncthreads();
        }
        buf ^= 1;
    }

    // epilogue: bias + relu -> g_H1
    #pragma unroll
    for (int i = 0; i < 8; i++) {
        const size_t row = (size_t)(rowBase + tr * 8 + i);
        #pragma unroll
        for (int j4 = 0; j4 < 8; j4 += 4) {
            const int col = colBase + tc * 8 + j4;
            float4 v;
            v.x = fmaxf(acc[i][j4 + 0] + b1[col + 0], 0.f);
            v.y = fmaxf(acc[i][j4 + 1] + b1[col + 1], 0.f);
            v.z = fmaxf(acc[i][j4 + 2] + b1[col + 2], 0.f);
            v.w = fmaxf(acc[i][j4 + 3] + b1[col + 3], 0.f);
            *(float4*)&g_H1[row * 256 + col] = v;
        }
    }
}

// ---------------------------------------------------------------------------
// Kernel 3: fused  h2 = relu(H1 @ W2 + b2) ; h3 = relu(h2 @ W3 + b3) ; out = h3 @ Wp + bp
// One block = 128 rows x all 128 cols of layer 2. h2 stays in smem (pad 132),
// then layer3 + head computed in-block. Dynamic smem ~130 KB.
// ---------------------------------------------------------------------------
#define SM3_AS  0
#define SM3_BS  4096
#define SM3_W3  8192
#define SM3_H2  16384
#define SM3_FLOATS (16384 + 128 * 132)
#define SM3_BYTES  (SM3_FLOATS * 4)

__global__ __launch_bounds__(256) void k_gemm2_tail(
    const float* __restrict__ W2, const float* __restrict__ b2,
    const float* __restrict__ W3, const float* __restrict__ b3,
    const float* __restrict__ Wp, const float* __restrict__ bp,
    float* __restrict__ out)
{
    extern __shared__ float smem[];
    float* AsF = smem + SM3_AS;  // [2][16][128]
    float* BsF = smem + SM3_BS;  // [2][16][128]
    float* W3s = smem + SM3_W3;  // [128][64]
    float* h2s = smem + SM3_H2;  // [128][132] padded

    const int tid = threadIdx.x;
    const int rowBase = blockIdx.x * 128;
    const int tr = tid >> 4, tc = tid & 15;

    // preload W3 into smem (8192 floats)
    #pragma unroll
    for (int i = 0; i < 8; i++)
        ((float4*)W3s)[tid + i * 256] = ((const float4*)W3)[tid + i * 256];

    const int ar0 = tid >> 2,          ac0 = (tid & 3) * 4;
    const int ar1 = (tid + 256) >> 2,  ac1 = ((tid + 256) & 3) * 4;
    const int br0 = tid >> 5,          bc0 = (tid & 31) * 4;
    const int br1 = (tid + 256) >> 5,  bc1 = ((tid + 256) & 31) * 4;

    const float* Ap = g_H1 + (size_t)rowBase * 256;

    float acc[8][8];
    #pragma unroll
    for (int i = 0; i < 8; i++)
        #pragma unroll
        for (int j = 0; j < 8; j++) acc[i][j] = 0.f;

    float4 va0, va1, vb0, vb1;
    va0 = *(const float4*)(Ap + (size_t)ar0 * 256 + ac0);
    va1 = *(const float4*)(Ap + (size_t)ar1 * 256 + ac1);
    vb0 = *(const float4*)(W2 + (size_t)br0 * 128 + bc0);
    vb1 = *(const float4*)(W2 + (size_t)br1 * 128 + bc1);
    AsF[(ac0 + 0) * 128 + ar0] = va0.x; AsF[(ac0 + 1) * 128 + ar0] = va0.y;
    AsF[(ac0 + 2) * 128 + ar0] = va0.z; AsF[(ac0 + 3) * 128 + ar0] = va0.w;
    AsF[(ac1 + 0) * 128 + ar1] = va1.x; AsF[(ac1 + 1) * 128 + ar1] = va1.y;
    AsF[(ac1 + 2) * 128 + ar1] = va1.z; AsF[(ac1 + 3) * 128 + ar1] = va1.w;
    *(float4*)&BsF[br0 * 128 + bc0] = vb0;
    *(float4*)&BsF[br1 * 128 + bc1] = vb1;
    __syncthreads();

    int buf = 0;
    const int NT = 256 / 16;  // 16
    for (int kt = 0; kt < NT; kt++) {
        const int kNext = (kt + 1) * 16;
        if (kt + 1 < NT) {
            va0 = *(const float4*)(Ap + (size_t)ar0 * 256 + kNext + ac0);
            va1 = *(const float4*)(Ap + (size_t)ar1 * 256 + kNext + ac1);
            vb0 = *(const float4*)(W2 + (size_t)(kNext + br0) * 128 + bc0);
            vb1 = *(const float4*)(W2 + (size_t)(kNext + br1) * 128 + bc1);
        }
        const float* Ab = AsF + buf * 2048;
        const float* Bb = BsF + buf * 2048;
        #pragma unroll
        for (int k = 0; k < 16; k++) {
            float4 fa0 = *(const float4*)&Ab[k * 128 + tr * 8];
            float4 fa1 = *(const float4*)&Ab[k * 128 + tr * 8 + 4];
            float4 fb0 = *(const float4*)&Bb[k * 128 + tc * 8];
            float4 fb1 = *(const float4*)&Bb[k * 128 + tc * 8 + 4];
            float a[8] = {fa0.x, fa0.y, fa0.z, fa0.w, fa1.x, fa1.y, fa1.z, fa1.w};
            float bb[8] = {fb0.x, fb0.y, fb0.z, fb0.w, fb1.x, fb1.y, fb1.z, fb1.w};
            #pragma unroll
            for (int i = 0; i < 8; i++)
                #pragma unroll
                for (int j = 0; j < 8; j++)
                    acc[i][j] = fmaf(a[i], bb[j], acc[i][j]);
        }
        if (kt + 1 < NT) {
            int nb = buf ^ 1;
            float* Aw = AsF + nb * 2048;
            float* Bw = BsF + nb * 2048;
            Aw[(ac0 + 0) * 128 + ar0] = va0.x; Aw[(ac0 + 1) * 128 + ar0] = va0.y;
            Aw[(ac0 + 2) * 128 + ar0] = va0.z; Aw[(ac0 + 3) * 128 + ar0] = va0.w;
            Aw[(ac1 + 0) * 128 + ar1] = va1.x; Aw[(ac1 + 1) * 128 + ar1] = va1.y;
            Aw[(ac1 + 2) * 128 + ar1] = va1.z; Aw[(ac1 + 3) * 128 + ar1] = va1.w;
            *(float4*)&Bw[br0 * 128 + bc0] = vb0;
            *(float4*)&Bw[br1 * 128 + bc1] = vb1;
            __syncthreads();
        }
        buf ^= 1;
    }

    // h2 = relu(acc + b2) -> smem (padded stride 132)
    #pragma unroll
    for (int i = 0; i < 8; i++) {
        const int r = tr * 8 + i;
        #pragma unroll
        for (int j = 0; j < 8; j++) {
            const int c = tc * 8 + j;
            h2s[r * 132 + c] = fmaxf(acc[i][j] + b2[c], 0.f);
        }
    }
    __syncthreads();

    // layer 3 + head: thread (row = tid/2, half = tid&1) computes 32 h3 cols
    {
        const int row = tid >> 1, half = tid & 1;
        const float* h2row = h2s + row * 132;
        float psum = 0.f;
        #pragma unroll 1
        for (int c = 0; c < 32; c++) {
            const int cc = half * 32 + c;
            float acc3 = __ldg(&b3[cc]);
            #pragma unroll
            for (int i = 0; i < 128; i += 4) {
                float4 h = *(const float4*)(h2row + i);
                acc3 = fmaf(h.x, W3s[(i + 0) * 64 + cc], acc3);
                acc3 = fmaf(h.y, W3s[(i + 1) * 64 + cc], acc3);
                acc3 = fmaf(h.z, W3s[(i + 2) * 64 + cc], acc3);
                acc3 = fmaf(h.w, W3s[(i + 3) * 64 + cc], acc3);
            }
            acc3 = fmaxf(acc3, 0.f);
            psum = fmaf(acc3, __ldg(&Wp[cc]), psum);
        }
        psum += __shfl_xor_sync(0xffffffffu, psum, 1);
        if (half == 0) out[rowBase + row] = psum + __ldg(bp);
    }
}

// ---------------------------------------------------------------------------
extern "C" void kernel_launch(void* const* d_in, const int* in_sizes, int n_in,
                              void* d_out, int out_size)
{
    const int*   user = (const int*)d_in[0];
    const int*   item = (const int*)d_in[1];
    const int*   pk   = (const int*)d_in[2];
    const int*   tk   = (const int*)d_in[3];
    const int*   ik   = (const int*)d_in[4];
    const int*   vp   = (const int*)d_in[5];
    const int*   vt   = (const int*)d_in[6];
    const int*   vi   = (const int*)d_in[7];
    const float* eu   = (const float*)d_in[8];
    const float* ei   = (const float*)d_in[9];
    const float* ek   = (const float*)d_in[10];
    const float* W1   = (const float*)d_in[11];
    const float* b1   = (const float*)d_in[12];
    const float* W2   = (const float*)d_in[13];
    const float* b2   = (const float*)d_in[14];
    const float* W3   = (const float*)d_in[15];
    const float* b3   = (const float*)d_in[16];
    const float* Wp   = (const float*)d_in[17];
    const float* bp   = (const float*)d_in[18];
    float* out = (float*)d_out;

    cudaFuncSetAttribute(k_gemm2_tail, cudaFuncAttributeMaxDynamicSharedMemorySize, SM3_BYTES);

    k_assemble<<<NB, 160>>>(user, item, pk, tk, ik, vp, vt, vi, eu, ei, ek);
    k_gemm1<<<dim3(NB / 128, 2), 256>>>(W1, b1);
    k_gemm2_tail<<<NB / 128, 256, SM3_BYTES>>>(W2, b2, W3, b3, Wp, bp, out);
}

// round 4
// speedup vs baseline: 1.5284x; 1.5284x over previous
#include <cuda_runtime.h>
#include <cuda_bf16.h>
#include <cstdint>

#define NB 65536
#define KK 20

// ---------------- device scratch (allocation-free rule) ----------------
__device__ __nv_bfloat16 g_Xhi[(size_t)NB * 448];
__device__ __nv_bfloat16 g_Xlo[(size_t)NB * 448];
__device__ __nv_bfloat16 g_H1hi[(size_t)NB * 256];
__device__ __nv_bfloat16 g_H1lo[(size_t)NB * 256];
__device__ __nv_bfloat16 g_W1Thi[256 * 448];
__device__ __nv_bfloat16 g_W1Tlo[256 * 448];
__device__ __nv_bfloat16 g_W2Thi[128 * 256];
__device__ __nv_bfloat16 g_W2Tlo[128 * 256];

// ---------------- helpers ----------------
__device__ __forceinline__ uint32_t smem_u32(const void* p) {
    uint32_t a;
    asm("{ .reg .u64 t; cvta.to.shared.u64 t, %1; cvt.u32.u64 %0, t; }" : "=r"(a) : "l"(p));
    return a;
}
__device__ __forceinline__ void cpasync16(uint32_t s, const void* g) {
    asm volatile("cp.async.cg.shared.global [%0], [%1], 16;" :: "r"(s), "l"(g));
}
#define CP_COMMIT() asm volatile("cp.async.commit_group;" ::: "memory")
#define CP_WAIT(n)  asm volatile("cp.async.wait_group %0;" :: "n"(n) : "memory")

__device__ __forceinline__ void ldsm4(uint32_t* r, uint32_t addr) {
    asm volatile("ldmatrix.sync.aligned.m8n8.x4.shared.b16 {%0,%1,%2,%3}, [%4];"
        : "=r"(r[0]), "=r"(r[1]), "=r"(r[2]), "=r"(r[3]) : "r"(addr));
}
__device__ __forceinline__ void ldsm2(uint32_t* r, uint32_t addr) {
    asm volatile("ldmatrix.sync.aligned.m8n8.x2.shared.b16 {%0,%1}, [%2];"
        : "=r"(r[0]), "=r"(r[1]) : "r"(addr));
}
__device__ __forceinline__ void mma16816(float* c, const uint32_t* a, const uint32_t* b) {
    asm volatile("mma.sync.aligned.m16n8k16.row.col.f32.bf16.bf16.f32 "
        "{%0,%1,%2,%3}, {%4,%5,%6,%7}, {%8,%9}, {%0,%1,%2,%3};"
        : "+f"(c[0]), "+f"(c[1]), "+f"(c[2]), "+f"(c[3])
        : "r"(a[0]), "r"(a[1]), "r"(a[2]), "r"(a[3]), "r"(b[0]), "r"(b[1]));
}

__device__ __forceinline__ void bf16split(float v, __nv_bfloat16& h, __nv_bfloat16& l) {
    h = __float2bfloat16_rn(v);
    l = __float2bfloat16_rn(v - __bfloat162float(h));
}
__device__ __forceinline__ void store4(__nv_bfloat16* ph, __nv_bfloat16* pl, float4 v) {
    __nv_bfloat16 h0, l0, h1, l1, h2, l2, h3, l3;
    bf16split(v.x, h0, l0); bf16split(v.y, h1, l1);
    bf16split(v.z, h2, l2); bf16split(v.w, h3, l3);
    ((__nv_bfloat162*)ph)[0] = __nv_bfloat162(h0, h1);
    ((__nv_bfloat162*)ph)[1] = __nv_bfloat162(h2, h3);
    ((__nv_bfloat162*)pl)[0] = __nv_bfloat162(l0, l1);
    ((__nv_bfloat162*)pl)[1] = __nv_bfloat162(l2, l3);
}

// smem tile geometry: 128 rows x 32 bf16, padded row stride 40 (80B, conflict-free)
#define TROW     40
#define PLANE_B  (128 * TROW * 2)     // 10240 bytes
#define BUF_B    (4 * PLANE_B)        // A_hi A_lo B_hi B_lo = 40960
#define PIPE_B   (2 * BUF_B)          // 81920

// ---------------------------------------------------------------------------
// Prep: W1[448,256] -> W1T[256][448] bf16 hi/lo ; W2[256,128] -> W2T[128][256]
// ---------------------------------------------------------------------------
__global__ void k_prep(const float* __restrict__ W1, const float* __restrict__ W2) {
    int tid = blockIdx.x * blockDim.x + threadIdx.x;
    if (tid < 448 * 256) {
        int k = tid >> 8, n = tid & 255;
        __nv_bfloat16 h, l; bf16split(W1[tid], h, l);
        g_W1Thi[n * 448 + k] = h; g_W1Tlo[n * 448 + k] = l;
    } else if (tid < 448 * 256 + 256 * 128) {
        int t = tid - 448 * 256;
        int k = t >> 7, n = t & 127;
        __nv_bfloat16 h, l; bf16split(W2[t], h, l);
        g_W2Thi[n * 256 + k] = h; g_W2Tlo[n * 256 + k] = l;
    }
}

// ---------------------------------------------------------------------------
// Assemble: X row = [eu | ei | mean_p | mean_t | mean_ik] -> bf16 hi/lo planes
// ---------------------------------------------------------------------------
__global__ __launch_bounds__(160) void k_assemble(
    const int* __restrict__ user, const int* __restrict__ item,
    const int* __restrict__ pk, const int* __restrict__ tk, const int* __restrict__ ik,
    const int* __restrict__ vp, const int* __restrict__ vt, const int* __restrict__ vi,
    const float* __restrict__ eu, const float* __restrict__ ei, const float* __restrict__ ek)
{
    int b = blockIdx.x;
    int w = threadIdx.x >> 5, lane = threadIdx.x & 31;
    __nv_bfloat16* Xh = g_Xhi + (size_t)b * 448;
    __nv_bfloat16* Xl = g_Xlo + (size_t)b * 448;

    if (w == 0) {
        float4 v = ((const float4*)(eu + (size_t)user[b] * 128))[lane];
        store4(Xh + lane * 4, Xl + lane * 4, v);
    } else if (w == 1) {
        float4 v = ((const float4*)(ei + (size_t)item[b] * 128))[lane];
        store4(Xh + 128 + lane * 4, Xl + 128 + lane * 4, v);
    } else {
        const int* idx; int valid; int off;
        if (w == 2)      { idx = pk; valid = vp[b]; off = 256; }
        else if (w == 3) { idx = tk; valid = vt[b]; off = 320; }
        else             { idx = ik; valid = vi[b]; off = 384; }
        int d = lane & 15, ko = lane >> 4;
        float4 acc = make_float4(0.f, 0.f, 0.f, 0.f);
        for (int k = ko; k < valid; k += 2) {
            int r = idx[b * KK + k];
            float4 v = ((const float4*)(ek + (size_t)r * 64))[d];
            acc.x += v.x; acc.y += v.y; acc.z += v.z; acc.w += v.w;
        }
        acc.x += __shfl_xor_sync(0xffffffffu, acc.x, 16);
        acc.y += __shfl_xor_sync(0xffffffffu, acc.y, 16);
        acc.z += __shfl_xor_sync(0xffffffffu, acc.z, 16);
        acc.w += __shfl_xor_sync(0xffffffffu, acc.w, 16);
        if (lane < 16) {
            float s = (valid > 0) ? (1.f / (float)valid) : 0.f;
            acc.x *= s; acc.y *= s; acc.z *= s; acc.w *= s;
            store4(Xh + off + d * 4, Xl + off + d * 4, acc);
        }
    }
}

// ---------------------------------------------------------------------------
// bf16x3 MMA core: CTA tile 128(M) x 128(N), K chunks of 32, double-buffered
// cp.async. 8 warps: wm = w&3 (M), wn = w>>2 (N). Warp tile 32x64.
// acc[mt 2][nt 8][4]. Ahi/Alo/Bhi/Blo pre-offset to tile origin.
// ---------------------------------------------------------------------------
template<int LDA, int LDB, int NC>
__device__ __forceinline__ void gemm_core(
    char* smem, uint32_t sb,
    const __nv_bfloat16* __restrict__ Ahi, const __nv_bfloat16* __restrict__ Alo,
    const __nv_bfloat16* __restrict__ Bhi, const __nv_bfloat16* __restrict__ Blo,
    float acc[2][8][4])
{
    const int tid = threadIdx.x;
    const int lane = tid & 31, w = tid >> 5;
    const int wm = w & 3, wn = w >> 2;

    // chunk loader
    auto load_chunk = [&](int buf, int kc) {
        const uint32_t base = sb + buf * BUF_B;
        #pragma unroll
        for (int i = tid; i < 512; i += 256) {
            int row = i >> 2, seg = i & 3;
            uint32_t so = base + (uint32_t)(row * TROW + seg * 8) * 2;
            int go = kc * 32 + seg * 8;
            cpasync16(so,               Ahi + (size_t)row * LDA + go);
            cpasync16(so + PLANE_B,     Alo + (size_t)row * LDA + go);
            cpasync16(so + 2 * PLANE_B, Bhi + (size_t)row * LDB + go);
            cpasync16(so + 3 * PLANE_B, Blo + (size_t)row * LDB + go);
        }
        CP_COMMIT();
    };

    load_chunk(0, 0);

    for (int kc = 0; kc < NC; kc++) {
        if (kc + 1 < NC) { load_chunk((kc + 1) & 1, kc + 1); CP_WAIT(1); }
        else             { CP_WAIT(0); }
        __syncthreads();

        const uint32_t bA = sb + (kc & 1) * BUF_B;
        const uint32_t bB = bA + 2 * PLANE_B;
        #pragma unroll
        for (int ks = 0; ks < 2; ks++) {
            const int k0 = ks * 16;
            uint32_t aoff = (uint32_t)((wm * 32 + (lane & 15)) * TROW + k0 + (lane >> 4) * 8) * 2;
            uint32_t ah[2][4], al[2][4];
            ldsm4(ah[0], bA + aoff);
            ldsm4(ah[1], bA + aoff + 16 * TROW * 2);
            ldsm4(al[0], bA + PLANE_B + aoff);
            ldsm4(al[1], bA + PLANE_B + aoff + 16 * TROW * 2);

            uint32_t boff = (uint32_t)((wn * 64 + (lane & 7)) * TROW + k0 + ((lane >> 3) & 1) * 8) * 2;
            uint32_t bh[8][2], bl[8][2];
            #pragma unroll
            for (int nt = 0; nt < 8; nt++) {
                ldsm2(bh[nt], bB + boff + nt * 8 * TROW * 2);
                ldsm2(bl[nt], bB + PLANE_B + boff + nt * 8 * TROW * 2);
            }
            #pragma unroll
            for (int mt = 0; mt < 2; mt++)
                #pragma unroll
                for (int nt = 0; nt < 8; nt++) {
                    mma16816(acc[mt][nt], ah[mt], bh[nt]);
                    mma16816(acc[mt][nt], ah[mt], bl[nt]);
                    mma16816(acc[mt][nt], al[mt], bh[nt]);
                }
        }
        __syncthreads();
    }
}

// ---------------------------------------------------------------------------
// GEMM1: H1 = relu(X @ W1 + b1)   grid (512, 2)
// ---------------------------------------------------------------------------
__global__ __launch_bounds__(256) void k_gemm1(const float* __restrict__ b1)
{
    extern __shared__ char smem[];
    const uint32_t sb = smem_u32(smem);
    const size_t rowBase = (size_t)blockIdx.x * 128;
    const int colBase = blockIdx.y * 128;

    float acc[2][8][4];
    #pragma unroll
    for (int a = 0; a < 2; a++)
        #pragma unroll
        for (int b = 0; b < 8; b++)
            #pragma unroll
            for (int c = 0; c < 4; c++) acc[a][b][c] = 0.f;

    gemm_core<448, 448, 14>(smem, sb,
        g_Xhi + rowBase * 448, g_Xlo + rowBase * 448,
        g_W1Thi + (size_t)colBase * 448, g_W1Tlo + (size_t)colBase * 448, acc);

    // epilogue: bias + relu + bf16 split -> g_H1 planes
    const int tid = threadIdx.x, lane = tid & 31, w = tid >> 5;
    const int wm = w & 3, wn = w >> 2, grp = lane >> 2, tig = lane & 3;
    #pragma unroll
    for (int mt = 0; mt < 2; mt++) {
        const size_t r0 = rowBase + wm * 32 + mt * 16 + grp;
        #pragma unroll
        for (int nt = 0; nt < 8; nt++) {
            const int c = colBase + wn * 64 + nt * 8 + tig * 2;
            float bb0 = __ldg(b1 + c), bb1 = __ldg(b1 + c + 1);
            float v00 = fmaxf(acc[mt][nt][0] + bb0, 0.f);
            float v01 = fmaxf(acc[mt][nt][1] + bb1, 0.f);
            float v10 = fmaxf(acc[mt][nt][2] + bb0, 0.f);
            float v11 = fmaxf(acc[mt][nt][3] + bb1, 0.f);
            __nv_bfloat16 h0, l0, h1, l1;
            bf16split(v00, h0, l0); bf16split(v01, h1, l1);
            *(__nv_bfloat162*)(g_H1hi + r0 * 256 + c) = __nv_bfloat162(h0, h1);
            *(__nv_bfloat162*)(g_H1lo + r0 * 256 + c) = __nv_bfloat162(l0, l1);
            bf16split(v10, h0, l0); bf16split(v11, h1, l1);
            *(__nv_bfloat162*)(g_H1hi + (r0 + 8) * 256 + c) = __nv_bfloat162(h0, h1);
            *(__nv_bfloat162*)(g_H1lo + (r0 + 8) * 256 + c) = __nv_bfloat162(l0, l1);
        }
    }
}

// ---------------------------------------------------------------------------
// GEMM2 + tail: h2 = relu(H1@W2+b2); h3 = relu(h2@W3+b3); out = h3@Wp+bp
// smem: [0, PIPE_B) pipeline (reused as h2s after math), [PIPE_B, +32KB) W3s
// ---------------------------------------------------------------------------
#define G2_W3S   PIPE_B
#define G2_BYTES (PIPE_B + 32768)

__global__ __launch_bounds__(256) void k_gemm2_tail(
    const float* __restrict__ b2, const float* __restrict__ W3,
    const float* __restrict__ b3, const float* __restrict__ Wp,
    const float* __restrict__ bp, float* __restrict__ out)
{
    extern __shared__ char smem[];
    const uint32_t sb = smem_u32(smem);
    float* W3s = (float*)(smem + G2_W3S);
    float* h2s = (float*)smem;                 // reused after pipeline done
    const int tid = threadIdx.x;
    const size_t rowBase = (size_t)blockIdx.x * 128;

    // preload W3 (8192 floats)
    for (int i = tid; i < 2048; i += 256)
        ((float4*)W3s)[i] = ((const float4*)W3)[i];

    float acc[2][8][4];
    #pragma unroll
    for (int a = 0; a < 2; a++)
        #pragma unroll
        for (int b = 0; b < 8; b++)
            #pragma unroll
            for (int c = 0; c < 4; c++) acc[a][b][c] = 0.f;

    gemm_core<256, 256, 8>(smem, sb,
        g_H1hi + rowBase * 256, g_H1lo + rowBase * 256,
        g_W2Thi, g_W2Tlo, acc);

    // h2 = relu(acc + b2) -> smem (stride 132)
    {
        const int lane = tid & 31, w = tid >> 5;
        const int wm = w & 3, wn = w >> 2, grp = lane >> 2, tig = lane & 3;
        #pragma unroll
        for (int mt = 0; mt < 2; mt++) {
            const int r = wm * 32 + mt * 16 + grp;
            #pragma unroll
            for (int nt = 0; nt < 8; nt++) {
                const int c = wn * 64 + nt * 8 + tig * 2;
                float bb0 = __ldg(b2 + c), bb1 = __ldg(b2 + c + 1);
                h2s[r * 132 + c]           = fmaxf(acc[mt][nt][0] + bb0, 0.f);
                h2s[r * 132 + c + 1]       = fmaxf(acc[mt][nt][1] + bb1, 0.f);
                h2s[(r + 8) * 132 + c]     = fmaxf(acc[mt][nt][2] + bb0, 0.f);
                h2s[(r + 8) * 132 + c + 1] = fmaxf(acc[mt][nt][3] + bb1, 0.f);
            }
        }
    }
    __syncthreads();

    // layer 3 + head (fp32): thread (row = tid/2, half = tid&1) -> 32 h3 cols
    {
        const int row = tid >> 1, half = tid & 1;
        const float* h2row = h2s + row * 132;
        float psum = 0.f;
        #pragma unroll 1
        for (int c = 0; c < 32; c++) {
            const int cc = half * 32 + c;
            float acc3 = __ldg(&b3[cc]);
            #pragma unroll
            for (int i = 0; i < 128; i += 4) {
                float4 h = *(const float4*)(h2row + i);
                acc3 = fmaf(h.x, W3s[(i + 0) * 64 + cc], acc3);
                acc3 = fmaf(h.y, W3s[(i + 1) * 64 + cc], acc3);
                acc3 = fmaf(h.z, W3s[(i + 2) * 64 + cc], acc3);
                acc3 = fmaf(h.w, W3s[(i + 3) * 64 + cc], acc3);
            }
            acc3 = fmaxf(acc3, 0.f);
            psum = fmaf(acc3, __ldg(&Wp[cc]), psum);
        }
        psum += __shfl_xor_sync(0xffffffffu, psum, 1);
        if (half == 0) out[rowBase + row] = psum + __ldg(bp);
    }
}

// ---------------------------------------------------------------------------
extern "C" void kernel_launch(void* const* d_in, const int* in_sizes, int n_in,
                              void* d_out, int out_size)
{
    const int*   user = (const int*)d_in[0];
    const int*   item = (const int*)d_in[1];
    const int*   pk   = (const int*)d_in[2];
    const int*   tk   = (const int*)d_in[3];
    const int*   ik   = (const int*)d_in[4];
    const int*   vp   = (const int*)d_in[5];
    const int*   vt   = (const int*)d_in[6];
    const int*   vi   = (const int*)d_in[7];
    const float* eu   = (const float*)d_in[8];
    const float* ei   = (const float*)d_in[9];
    const float* ek   = (const float*)d_in[10];
    const float* W1   = (const float*)d_in[11];
    const float* b1   = (const float*)d_in[12];
    const float* W2   = (const float*)d_in[13];
    const float* b2   = (const float*)d_in[14];
    const float* W3   = (const float*)d_in[15];
    const float* b3   = (const float*)d_in[16];
    const float* Wp   = (const float*)d_in[17];
    const float* bp   = (const float*)d_in[18];
    float* out = (float*)d_out;

    cudaFuncSetAttribute(k_gemm1,      cudaFuncAttributeMaxDynamicSharedMemorySize, PIPE_B);
    cudaFuncSetAttribute(k_gemm2_tail, cudaFuncAttributeMaxDynamicSharedMemorySize, G2_BYTES);

    k_prep<<<(448 * 256 + 256 * 128 + 255) / 256, 256>>>(W1, W2);
    k_assemble<<<NB, 160>>>(user, item, pk, tk, ik, vp, vt, vi, eu, ei, ek);
    k_gemm1<<<dim3(NB / 128, 2), 256, PIPE_B>>>(b1);
    k_gemm2_tail<<<NB / 128, 256, G2_BYTES>>>(b2, W3, b3, Wp, bp, out);
}

// round 5
// speedup vs baseline: 2.2115x; 1.4469x over previous
#include <cuda_runtime.h>
#include <cuda_bf16.h>
#include <cstdint>

#define NB 65536
#define KK 20

// ---------------- device scratch (allocation-free rule) ----------------
__device__ __nv_bfloat16 g_Xhi[(size_t)NB * 448];
__device__ __nv_bfloat16 g_Xlo[(size_t)NB * 448];
__device__ __nv_bfloat16 g_H1hi[(size_t)NB * 256];
__device__ __nv_bfloat16 g_H1lo[(size_t)NB * 256];
__device__ __nv_bfloat16 g_W1Thi[256 * 448];
__device__ __nv_bfloat16 g_W1Tlo[256 * 448];
__device__ __nv_bfloat16 g_W2Thi[128 * 256];
__device__ __nv_bfloat16 g_W2Tlo[128 * 256];
__device__ __nv_bfloat16 g_W3Thi[64 * 128];
__device__ __nv_bfloat16 g_W3Tlo[64 * 128];

// ---------------- helpers ----------------
__device__ __forceinline__ uint32_t smem_u32(const void* p) {
    uint32_t a;
    asm("{ .reg .u64 t; cvta.to.shared.u64 t, %1; cvt.u32.u64 %0, t; }" : "=r"(a) : "l"(p));
    return a;
}
__device__ __forceinline__ void cpasync16(uint32_t s, const void* g) {
    asm volatile("cp.async.cg.shared.global [%0], [%1], 16;" :: "r"(s), "l"(g));
}
#define CP_COMMIT() asm volatile("cp.async.commit_group;" ::: "memory")
#define CP_WAIT(n)  asm volatile("cp.async.wait_group %0;" :: "n"(n) : "memory")

__device__ __forceinline__ void ldsm4(uint32_t* r, uint32_t addr) {
    asm volatile("ldmatrix.sync.aligned.m8n8.x4.shared.b16 {%0,%1,%2,%3}, [%4];"
        : "=r"(r[0]), "=r"(r[1]), "=r"(r[2]), "=r"(r[3]) : "r"(addr));
}
__device__ __forceinline__ void mma16816(float* c, const uint32_t* a, const uint32_t* b) {
    asm volatile("mma.sync.aligned.m16n8k16.row.col.f32.bf16.bf16.f32 "
        "{%0,%1,%2,%3}, {%4,%5,%6,%7}, {%8,%9}, {%0,%1,%2,%3};"
        : "+f"(c[0]), "+f"(c[1]), "+f"(c[2]), "+f"(c[3])
        : "r"(a[0]), "r"(a[1]), "r"(a[2]), "r"(a[3]), "r"(b[0]), "r"(b[1]));
}

__device__ __forceinline__ void bf16split(float v, __nv_bfloat16& h, __nv_bfloat16& l) {
    h = __float2bfloat16_rn(v);
    l = __float2bfloat16_rn(v - __bfloat162float(h));
}
__device__ __forceinline__ void store4(__nv_bfloat16* ph, __nv_bfloat16* pl, float4 v) {
    __nv_bfloat16 h0, l0, h1, l1, h2, l2, h3, l3;
    bf16split(v.x, h0, l0); bf16split(v.y, h1, l1);
    bf16split(v.z, h2, l2); bf16split(v.w, h3, l3);
    ((__nv_bfloat162*)ph)[0] = __nv_bfloat162(h0, h1);
    ((__nv_bfloat162*)ph)[1] = __nv_bfloat162(h2, h3);
    ((__nv_bfloat162*)pl)[0] = __nv_bfloat162(l0, l1);
    ((__nv_bfloat162*)pl)[1] = __nv_bfloat162(l2, l3);
}

// smem tile geometry: 128 rows x 32 bf16, padded row stride 40 (80B, conflict-free)
#define TROW     40
#define PLANE_B  (128 * TROW * 2)     // 10240 bytes
#define BUF_B    (4 * PLANE_B)        // A_hi A_lo B_hi B_lo = 40960
#define PIPE_B   (2 * BUF_B)          // 81920

// layer-3 smem geometry (stride 136 bf16 = 272B, 17x16B -> ldmatrix conflict-free)
#define L3ROW    136
#define H2_PLANE (128 * L3ROW * 2)    // 34816 bytes
#define W3_PLANE (64 * L3ROW * 2)     // 17408 bytes
#define G2_W3S   PIPE_B               // W3T hi/lo after pipeline region
#define G2_SUM   (G2_W3S + 2 * W3_PLANE)
#define G2_BYTES (G2_SUM + 512 + 128)

// ---------------------------------------------------------------------------
// Prep: transpose + bf16-split W1, W2, W3
// ---------------------------------------------------------------------------
__global__ void k_prep(const float* __restrict__ W1, const float* __restrict__ W2,
                       const float* __restrict__ W3) {
    int tid = blockIdx.x * blockDim.x + threadIdx.x;
    if (tid < 448 * 256) {
        int k = tid >> 8, n = tid & 255;
        __nv_bfloat16 h, l; bf16split(W1[tid], h, l);
        g_W1Thi[n * 448 + k] = h; g_W1Tlo[n * 448 + k] = l;
    } else if (tid < 448 * 256 + 256 * 128) {
        int t = tid - 448 * 256;
        int k = t >> 7, n = t & 127;
        __nv_bfloat16 h, l; bf16split(W2[t], h, l);
        g_W2Thi[n * 256 + k] = h; g_W2Tlo[n * 256 + k] = l;
    } else if (tid < 448 * 256 + 256 * 128 + 64 * 128) {
        int t = tid - (448 * 256 + 256 * 128);
        int n = t >> 7, k = t & 127;
        __nv_bfloat16 h, l; bf16split(W3[k * 64 + n], h, l);
        g_W3Thi[n * 128 + k] = h; g_W3Tlo[n * 128 + k] = l;
    }
}

// ---------------------------------------------------------------------------
// Assemble: X row = [eu | ei | mean_p | mean_t | mean_ik] -> bf16 hi/lo planes
// ---------------------------------------------------------------------------
__global__ __launch_bounds__(160) void k_assemble(
    const int* __restrict__ user, const int* __restrict__ item,
    const int* __restrict__ pk, const int* __restrict__ tk, const int* __restrict__ ik,
    const int* __restrict__ vp, const int* __restrict__ vt, const int* __restrict__ vi,
    const float* __restrict__ eu, const float* __restrict__ ei, const float* __restrict__ ek)
{
    int b = blockIdx.x;
    int w = threadIdx.x >> 5, lane = threadIdx.x & 31;
    __nv_bfloat16* Xh = g_Xhi + (size_t)b * 448;
    __nv_bfloat16* Xl = g_Xlo + (size_t)b * 448;

    if (w == 0) {
        float4 v = ((const float4*)(eu + (size_t)user[b] * 128))[lane];
        store4(Xh + lane * 4, Xl + lane * 4, v);
    } else if (w == 1) {
        float4 v = ((const float4*)(ei + (size_t)item[b] * 128))[lane];
        store4(Xh + 128 + lane * 4, Xl + 128 + lane * 4, v);
    } else {
        const int* idx; int valid; int off;
        if (w == 2)      { idx = pk; valid = vp[b]; off = 256; }
        else if (w == 3) { idx = tk; valid = vt[b]; off = 320; }
        else             { idx = ik; valid = vi[b]; off = 384; }
        int d = lane & 15, ko = lane >> 4;
        float4 acc = make_float4(0.f, 0.f, 0.f, 0.f);
        for (int k = ko; k < valid; k += 2) {
            int r = idx[b * KK + k];
            float4 v = ((const float4*)(ek + (size_t)r * 64))[d];
            acc.x += v.x; acc.y += v.y; acc.z += v.z; acc.w += v.w;
        }
        acc.x += __shfl_xor_sync(0xffffffffu, acc.x, 16);
        acc.y += __shfl_xor_sync(0xffffffffu, acc.y, 16);
        acc.z += __shfl_xor_sync(0xffffffffu, acc.z, 16);
        acc.w += __shfl_xor_sync(0xffffffffu, acc.w, 16);
        if (lane < 16) {
            float s = (valid > 0) ? (1.f / (float)valid) : 0.f;
            acc.x *= s; acc.y *= s; acc.z *= s; acc.w *= s;
            store4(Xh + off + d * 4, Xl + off + d * 4, acc);
        }
    }
}

// ---------------------------------------------------------------------------
// bf16x3 MMA core: CTA tile 128(M) x 128(N), K chunks of 32, double-buffered
// cp.async. 8 warps: wm = w&3 (M), wn = w>>2 (N). Warp tile 32x64.
// B fragments fetched as ldsm4 pairs (2 n-tiles per ldmatrix).
// ---------------------------------------------------------------------------
template<int LDA, int LDB, int NC>
__device__ __forceinline__ void gemm_core(
    uint32_t sb,
    const __nv_bfloat16* __restrict__ Ahi, const __nv_bfloat16* __restrict__ Alo,
    const __nv_bfloat16* __restrict__ Bhi, const __nv_bfloat16* __restrict__ Blo,
    float acc[2][8][4])
{
    const int tid = threadIdx.x;
    const int lane = tid & 31, w = tid >> 5;
    const int wm = w & 3, wn = w >> 2;

    auto load_chunk = [&](int buf, int kc) {
        const uint32_t base = sb + buf * BUF_B;
        #pragma unroll
        for (int i = tid; i < 512; i += 256) {
            int row = i >> 2, seg = i & 3;
            uint32_t so = base + (uint32_t)(row * TROW + seg * 8) * 2;
            int go = kc * 32 + seg * 8;
            cpasync16(so,               Ahi + (size_t)row * LDA + go);
            cpasync16(so + PLANE_B,     Alo + (size_t)row * LDA + go);
            cpasync16(so + 2 * PLANE_B, Bhi + (size_t)row * LDB + go);
            cpasync16(so + 3 * PLANE_B, Blo + (size_t)row * LDB + go);
        }
        CP_COMMIT();
    };

    load_chunk(0, 0);

    for (int kc = 0; kc < NC; kc++) {
        if (kc + 1 < NC) { load_chunk((kc + 1) & 1, kc + 1); CP_WAIT(1); }
        else             { CP_WAIT(0); }
        __syncthreads();

        const uint32_t bA = sb + (kc & 1) * BUF_B;
        const uint32_t bB = bA + 2 * PLANE_B;
        #pragma unroll
        for (int ks = 0; ks < 2; ks++) {
            const int k0 = ks * 16;
            // A fragments (hi/lo), 2 m-tiles
            uint32_t aoff = (uint32_t)((wm * 32 + (lane & 15)) * TROW + k0 + (lane >> 4) * 8) * 2;
            uint32_t ah[2][4], al[2][4];
            ldsm4(ah[0], bA + aoff);
            ldsm4(ah[1], bA + aoff + 16 * TROW * 2);
            ldsm4(al[0], bA + PLANE_B + aoff);
            ldsm4(al[1], bA + PLANE_B + aoff + 16 * TROW * 2);

            // B fragments as ldsm4 pairs: pair p covers n-tiles 2p, 2p+1
            const int q = lane >> 3;
            uint32_t brow0 = (uint32_t)(wn * 64 + (q >> 1) * 8 + (lane & 7));
            uint32_t bcol  = (uint32_t)(k0 + (q & 1) * 8);
            uint32_t bh[8][2], bl[8][2];
            #pragma unroll
            for (int p = 0; p < 4; p++) {
                uint32_t off = ((brow0 + p * 16) * TROW + bcol) * 2;
                uint32_t t[4];
                ldsm4(t, bB + off);
                bh[2*p][0] = t[0]; bh[2*p][1] = t[1];
                bh[2*p+1][0] = t[2]; bh[2*p+1][1] = t[3];
                ldsm4(t, bB + PLANE_B + off);
                bl[2*p][0] = t[0]; bl[2*p][1] = t[1];
                bl[2*p+1][0] = t[2]; bl[2*p+1][1] = t[3];
            }
            #pragma unroll
            for (int mt = 0; mt < 2; mt++)
                #pragma unroll
                for (int nt = 0; nt < 8; nt++) {
                    mma16816(acc[mt][nt], ah[mt], bh[nt]);
                    mma16816(acc[mt][nt], ah[mt], bl[nt]);
                    mma16816(acc[mt][nt], al[mt], bh[nt]);
                }
        }
        __syncthreads();
    }
}

// ---------------------------------------------------------------------------
// GEMM1: H1 = relu(X @ W1 + b1)   grid (512, 2)
// ---------------------------------------------------------------------------
__global__ __launch_bounds__(256) void k_gemm1(const float* __restrict__ b1)
{
    extern __shared__ char smem[];
    const uint32_t sb = smem_u32(smem);
    const size_t rowBase = (size_t)blockIdx.x * 128;
    const int colBase = blockIdx.y * 128;

    float acc[2][8][4];
    #pragma unroll
    for (int a = 0; a < 2; a++)
        #pragma unroll
        for (int b = 0; b < 8; b++)
            #pragma unroll
            for (int c = 0; c < 4; c++) acc[a][b][c] = 0.f;

    gemm_core<448, 448, 14>(sb,
        g_Xhi + rowBase * 448, g_Xlo + rowBase * 448,
        g_W1Thi + (size_t)colBase * 448, g_W1Tlo + (size_t)colBase * 448, acc);

    const int tid = threadIdx.x, lane = tid & 31, w = tid >> 5;
    const int wm = w & 3, wn = w >> 2, grp = lane >> 2, tig = lane & 3;
    #pragma unroll
    for (int mt = 0; mt < 2; mt++) {
        const size_t r0 = rowBase + wm * 32 + mt * 16 + grp;
        #pragma unroll
        for (int nt = 0; nt < 8; nt++) {
            const int c = colBase + wn * 64 + nt * 8 + tig * 2;
            float bb0 = __ldg(b1 + c), bb1 = __ldg(b1 + c + 1);
            float v00 = fmaxf(acc[mt][nt][0] + bb0, 0.f);
            float v01 = fmaxf(acc[mt][nt][1] + bb1, 0.f);
            float v10 = fmaxf(acc[mt][nt][2] + bb0, 0.f);
            float v11 = fmaxf(acc[mt][nt][3] + bb1, 0.f);
            __nv_bfloat16 h0, l0, h1, l1;
            bf16split(v00, h0, l0); bf16split(v01, h1, l1);
            *(__nv_bfloat162*)(g_H1hi + r0 * 256 + c) = __nv_bfloat162(h0, h1);
            *(__nv_bfloat162*)(g_H1lo + r0 * 256 + c) = __nv_bfloat162(l0, l1);
            bf16split(v10, h0, l0); bf16split(v11, h1, l1);
            *(__nv_bfloat162*)(g_H1hi + (r0 + 8) * 256 + c) = __nv_bfloat162(h0, h1);
            *(__nv_bfloat162*)(g_H1lo + (r0 + 8) * 256 + c) = __nv_bfloat162(l0, l1);
        }
    }
}

// ---------------------------------------------------------------------------
// GEMM2 + MMA tail: h2 = relu(H1@W2+b2) -> smem bf16 planes;
// h3 = relu(h2@W3+b3) via bf16x3 HMMA; out = h3@Wp + bp via reduction.
// ---------------------------------------------------------------------------
__global__ __launch_bounds__(256) void k_gemm2_tail(
    const float* __restrict__ b2, const float* __restrict__ b3,
    const float* __restrict__ Wp, const float* __restrict__ bp,
    float* __restrict__ out)
{
    extern __shared__ char smem[];
    const uint32_t sb = smem_u32(smem);
    const int tid = threadIdx.x, lane = tid & 31, w = tid >> 5;
    const int wm = w & 3, wn = w >> 2, grp = lane >> 2, tig = lane & 3;
    const size_t rowBase = (size_t)blockIdx.x * 128;

    // preload W3T bf16 planes into padded smem (non-overlapping region)
    {
        char* w3dst = smem + G2_W3S;
        #pragma unroll
        for (int i = tid; i < 64 * 16; i += 256) {
            int row = i >> 4, u = i & 15;
            *(uint4*)(w3dst + (row * L3ROW + u * 8) * 2) =
                *(const uint4*)(g_W3Thi + row * 128 + u * 8);
            *(uint4*)(w3dst + W3_PLANE + (row * L3ROW + u * 8) * 2) =
                *(const uint4*)(g_W3Tlo + row * 128 + u * 8);
        }
    }

    float acc[2][8][4];
    #pragma unroll
    for (int a = 0; a < 2; a++)
        #pragma unroll
        for (int b = 0; b < 8; b++)
            #pragma unroll
            for (int c = 0; c < 4; c++) acc[a][b][c] = 0.f;

    gemm_core<256, 256, 8>(sb,
        g_H1hi + rowBase * 256, g_H1lo + rowBase * 256,
        g_W2Thi, g_W2Tlo, acc);

    // h2 = relu(acc + b2) -> smem bf16 hi/lo planes (stride L3ROW), reusing pipe region
    __nv_bfloat16* h2hi = (__nv_bfloat16*)smem;
    __nv_bfloat16* h2lo = (__nv_bfloat16*)(smem + H2_PLANE);
    float* h3sum = (float*)(smem + G2_SUM);
    {
        #pragma unroll
        for (int mt = 0; mt < 2; mt++) {
            const int r = wm * 32 + mt * 16 + grp;
            #pragma unroll
            for (int nt = 0; nt < 8; nt++) {
                const int c = wn * 64 + nt * 8 + tig * 2;
                float bb0 = __ldg(b2 + c), bb1 = __ldg(b2 + c + 1);
                float v00 = fmaxf(acc[mt][nt][0] + bb0, 0.f);
                float v01 = fmaxf(acc[mt][nt][1] + bb1, 0.f);
                float v10 = fmaxf(acc[mt][nt][2] + bb0, 0.f);
                float v11 = fmaxf(acc[mt][nt][3] + bb1, 0.f);
                __nv_bfloat16 h0, l0, h1, l1;
                bf16split(v00, h0, l0); bf16split(v01, h1, l1);
                *(__nv_bfloat162*)(h2hi + r * L3ROW + c) = __nv_bfloat162(h0, h1);
                *(__nv_bfloat162*)(h2lo + r * L3ROW + c) = __nv_bfloat162(l0, l1);
                bf16split(v10, h0, l0); bf16split(v11, h1, l1);
                *(__nv_bfloat162*)(h2hi + (r + 8) * L3ROW + c) = __nv_bfloat162(h0, h1);
                *(__nv_bfloat162*)(h2lo + (r + 8) * L3ROW + c) = __nv_bfloat162(l0, l1);
            }
        }
    }
    if (tid < 128) h3sum[tid] = 0.f;
    __syncthreads();

    // layer 3 via bf16x3 HMMA: M=128 (wm), N=64 (wn covers 32 = 4 n-tiles), K=128
    float acc3[2][4][4];
    #pragma unroll
    for (int a = 0; a < 2; a++)
        #pragma unroll
        for (int b = 0; b < 4; b++)
            #pragma unroll
            for (int c = 0; c < 4; c++) acc3[a][b][c] = 0.f;

    const uint32_t hA = sb;                       // h2 hi plane
    const uint32_t hB = sb + G2_W3S;              // W3T hi plane
    #pragma unroll
    for (int kc = 0; kc < 8; kc++) {
        const int k0 = kc * 16;
        uint32_t aoff = (uint32_t)((wm * 32 + (lane & 15)) * L3ROW + k0 + (lane >> 4) * 8) * 2;
        uint32_t ah[2][4], al[2][4];
        ldsm4(ah[0], hA + aoff);
        ldsm4(ah[1], hA + aoff + 16 * L3ROW * 2);
        ldsm4(al[0], hA + H2_PLANE + aoff);
        ldsm4(al[1], hA + H2_PLANE + aoff + 16 * L3ROW * 2);

        const int q = lane >> 3;
        uint32_t brow0 = (uint32_t)(wn * 32 + (q >> 1) * 8 + (lane & 7));
        uint32_t bcol  = (uint32_t)(k0 + (q & 1) * 8);
        uint32_t bh[4][2], bl[4][2];
        #pragma unroll
        for (int p = 0; p < 2; p++) {
            uint32_t off = ((brow0 + p * 16) * L3ROW + bcol) * 2;
            uint32_t t[4];
            ldsm4(t, hB + off);
            bh[2*p][0] = t[0]; bh[2*p][1] = t[1];
            bh[2*p+1][0] = t[2]; bh[2*p+1][1] = t[3];
            ldsm4(t, hB + W3_PLANE + off);
            bl[2*p][0] = t[0]; bl[2*p][1] = t[1];
            bl[2*p+1][0] = t[2]; bl[2*p+1][1] = t[3];
        }
        #pragma unroll
        for (int mt = 0; mt < 2; mt++)
            #pragma unroll
            for (int nt = 0; nt < 4; nt++) {
                mma16816(acc3[mt][nt], ah[mt], bh[nt]);
                mma16816(acc3[mt][nt], ah[mt], bl[nt]);
                mma16816(acc3[mt][nt], al[mt], bh[nt]);
            }
    }

    // head: relu(h3 + b3) . Wp, reduce to per-row sums
    {
        float rs[2][2] = {{0.f, 0.f}, {0.f, 0.f}};
        #pragma unroll
        for (int nt = 0; nt < 4; nt++) {
            const int c = wn * 32 + nt * 8 + tig * 2;
            float bb0 = __ldg(b3 + c),  bb1 = __ldg(b3 + c + 1);
            float wp0 = __ldg(Wp + c),  wp1 = __ldg(Wp + c + 1);
            #pragma unroll
            for (int mt = 0; mt < 2; mt++) {
                rs[mt][0] += fmaxf(acc3[mt][nt][0] + bb0, 0.f) * wp0
                           + fmaxf(acc3[mt][nt][1] + bb1, 0.f) * wp1;
                rs[mt][1] += fmaxf(acc3[mt][nt][2] + bb0, 0.f) * wp0
                           + fmaxf(acc3[mt][nt][3] + bb1, 0.f) * wp1;
            }
        }
        #pragma unroll
        for (int mt = 0; mt < 2; mt++)
            #pragma unroll
            for (int h = 0; h < 2; h++) {
                rs[mt][h] += __shfl_xor_sync(0xffffffffu, rs[mt][h], 1);
                rs[mt][h] += __shfl_xor_sync(0xffffffffu, rs[mt][h], 2);
            }
        if (tig == 0) {
            #pragma unroll
            for (int mt = 0; mt < 2; mt++) {
                atomicAdd(&h3sum[wm * 32 + mt * 16 + grp],     rs[mt][0]);
                atomicAdd(&h3sum[wm * 32 + mt * 16 + grp + 8], rs[mt][1]);
            }
        }
    }
    __syncthreads();
    if (tid < 128) out[rowBase + tid] = h3sum[tid] + __ldg(bp);
}

// ---------------------------------------------------------------------------
extern "C" void kernel_launch(void* const* d_in, const int* in_sizes, int n_in,
                              void* d_out, int out_size)
{
    const int*   user = (const int*)d_in[0];
    const int*   item = (const int*)d_in[1];
    const int*   pk   = (const int*)d_in[2];
    const int*   tk   = (const int*)d_in[3];
    const int*   ik   = (const int*)d_in[4];
    const int*   vp   = (const int*)d_in[5];
    const int*   vt   = (const int*)d_in[6];
    const int*   vi   = (const int*)d_in[7];
    const float* eu   = (const float*)d_in[8];
    const float* ei   = (const float*)d_in[9];
    const float* ek   = (const float*)d_in[10];
    const float* W1   = (const float*)d_in[11];
    const float* b1   = (const float*)d_in[12];
    const float* W2   = (const float*)d_in[13];
    const float* b2   = (const float*)d_in[14];
    const float* W3   = (const float*)d_in[15];
    const float* b3   = (const float*)d_in[16];
    const float* Wp   = (const float*)d_in[17];
    const float* bp   = (const float*)d_in[18];
    float* out = (float*)d_out;

    cudaFuncSetAttribute(k_gemm1,      cudaFuncAttributeMaxDynamicSharedMemorySize, PIPE_B);
    cudaFuncSetAttribute(k_gemm2_tail, cudaFuncAttributeMaxDynamicSharedMemorySize, G2_BYTES);

    const int prep_n = 448 * 256 + 256 * 128 + 64 * 128;
    k_prep<<<(prep_n + 255) / 256, 256>>>(W1, W2, W3);
    k_assemble<<<NB, 160>>>(user, item, pk, tk, ik, vp, vt, vi, eu, ei, ek);
    k_gemm1<<<dim3(NB / 128, 2), 256, PIPE_B>>>(b1);
    k_gemm2_tail<<<NB / 128, 256, G2_BYTES>>>(b2, b3, Wp, bp, out);
}

// round 7
// speedup vs baseline: 2.5100x; 1.1350x over previous
#include <cuda_runtime.h>
#include <cuda_bf16.h>
#include <cstdint>

#define NB 65536
#define KK 20

// ---------------- device scratch (allocation-free rule) ----------------
__device__ __nv_bfloat16 g_Xhi[(size_t)NB * 448];
__device__ __nv_bfloat16 g_Xlo[(size_t)NB * 448];
__device__ __nv_bfloat16 g_H1hi[(size_t)NB * 256];
__device__ __nv_bfloat16 g_H1lo[(size_t)NB * 256];
__device__ __nv_bfloat16 g_W1Thi[256 * 448];
__device__ __nv_bfloat16 g_W1Tlo[256 * 448];
__device__ __nv_bfloat16 g_W2Thi[128 * 256];
__device__ __nv_bfloat16 g_W2Tlo[128 * 256];
__device__ __nv_bfloat16 g_W3Thi[64 * 128];
__device__ __nv_bfloat16 g_W3Tlo[64 * 128];

// ---------------- helpers ----------------
__device__ __forceinline__ uint32_t smem_u32(const void* p) {
    uint32_t a;
    asm("{ .reg .u64 t; cvta.to.shared.u64 t, %1; cvt.u32.u64 %0, t; }" : "=r"(a) : "l"(p));
    return a;
}
__device__ __forceinline__ void cpasync16(uint32_t s, const void* g) {
    asm volatile("cp.async.cg.shared.global [%0], [%1], 16;" :: "r"(s), "l"(g));
}
#define CP_COMMIT() asm volatile("cp.async.commit_group;" ::: "memory")
#define CP_WAIT(n)  asm volatile("cp.async.wait_group %0;" :: "n"(n) : "memory")

__device__ __forceinline__ void ldsm4(uint32_t* r, uint32_t addr) {
    asm volatile("ldmatrix.sync.aligned.m8n8.x4.shared.b16 {%0,%1,%2,%3}, [%4];"
        : "=r"(r[0]), "=r"(r[1]), "=r"(r[2]), "=r"(r[3]) : "r"(addr));
}
__device__ __forceinline__ void mma16816(float* c, const uint32_t* a, const uint32_t* b) {
    asm volatile("mma.sync.aligned.m16n8k16.row.col.f32.bf16.bf16.f32 "
        "{%0,%1,%2,%3}, {%4,%5,%6,%7}, {%8,%9}, {%0,%1,%2,%3};"
        : "+f"(c[0]), "+f"(c[1]), "+f"(c[2]), "+f"(c[3])
        : "r"(a[0]), "r"(a[1]), "r"(a[2]), "r"(a[3]), "r"(b[0]), "r"(b[1]));
}

__device__ __forceinline__ void bf16split(float v, __nv_bfloat16& h, __nv_bfloat16& l) {
    h = __float2bfloat16_rn(v);
    l = __float2bfloat16_rn(v - __bfloat162float(h));
}
__device__ __forceinline__ void store4(__nv_bfloat16* ph, __nv_bfloat16* pl, float4 v) {
    __nv_bfloat16 h0, l0, h1, l1, h2, l2, h3, l3;
    bf16split(v.x, h0, l0); bf16split(v.y, h1, l1);
    bf16split(v.z, h2, l2); bf16split(v.w, h3, l3);
    ((__nv_bfloat162*)ph)[0] = __nv_bfloat162(h0, h1);
    ((__nv_bfloat162*)ph)[1] = __nv_bfloat162(h2, h3);
    ((__nv_bfloat162*)pl)[0] = __nv_bfloat162(l0, l1);
    ((__nv_bfloat162*)pl)[1] = __nv_bfloat162(l2, l3);
}

// smem tile geometry: 128 rows x 32 bf16, padded row stride 40 (80B, conflict-free)
#define TROW     40
#define PLANE_B  (128 * TROW * 2)     // 10240 bytes
#define BUF_B    (4 * PLANE_B)        // A_hi A_lo B_hi B_lo = 40960
#define PIPE_B   (2 * BUF_B)          // 81920

// layer-3 smem geometry (h2 planes reuse pipe region; stride 136 bf16)
#define L3ROW    136
#define H2_PLANE (128 * L3ROW * 2)    // 34816 bytes (2 planes = 69632 <= PIPE_B)
#define G2_SUM   PIPE_B
#define G2_BYTES (PIPE_B + 512 + 128)

// ---------------------------------------------------------------------------
// Prep: transpose + bf16-split W1, W2, W3
// ---------------------------------------------------------------------------
__global__ void k_prep(const float* __restrict__ W1, const float* __restrict__ W2,
                       const float* __restrict__ W3) {
    int tid = blockIdx.x * blockDim.x + threadIdx.x;
    if (tid < 448 * 256) {
        int k = tid >> 8, n = tid & 255;
        __nv_bfloat16 h, l; bf16split(W1[tid], h, l);
        g_W1Thi[n * 448 + k] = h; g_W1Tlo[n * 448 + k] = l;
    } else if (tid < 448 * 256 + 256 * 128) {
        int t = tid - 448 * 256;
        int k = t >> 7, n = t & 127;
        __nv_bfloat16 h, l; bf16split(W2[t], h, l);
        g_W2Thi[n * 256 + k] = h; g_W2Tlo[n * 256 + k] = l;
    } else if (tid < 448 * 256 + 256 * 128 + 64 * 128) {
        int t = tid - (448 * 256 + 256 * 128);
        int n = t >> 7, k = t & 127;
        __nv_bfloat16 h, l; bf16split(W3[k * 64 + n], h, l);
        g_W3Thi[n * 128 + k] = h; g_W3Tlo[n * 128 + k] = l;
    }
}

// ---------------------------------------------------------------------------
// Assemble: X row = [eu | ei | mean_p | mean_t | mean_ik] -> bf16 hi/lo planes
// Index hoist with WARP-UNIFORM loop: all lanes run ceil(valid/2) iterations,
// shfl executed converged, gather predicated by k < valid.
// ---------------------------------------------------------------------------
__global__ __launch_bounds__(160) void k_assemble(
    const int* __restrict__ user, const int* __restrict__ item,
    const int* __restrict__ pk, const int* __restrict__ tk, const int* __restrict__ ik,
    const int* __restrict__ vp, const int* __restrict__ vt, const int* __restrict__ vi,
    const float* __restrict__ eu, const float* __restrict__ ei, const float* __restrict__ ek)
{
    int b = blockIdx.x;
    int w = threadIdx.x >> 5, lane = threadIdx.x & 31;
    __nv_bfloat16* Xh = g_Xhi + (size_t)b * 448;
    __nv_bfloat16* Xl = g_Xlo + (size_t)b * 448;

    if (w == 0) {
        float4 v = ((const float4*)(eu + (size_t)user[b] * 128))[lane];
        store4(Xh + lane * 4, Xl + lane * 4, v);
    } else if (w == 1) {
        float4 v = ((const float4*)(ei + (size_t)item[b] * 128))[lane];
        store4(Xh + 128 + lane * 4, Xl + 128 + lane * 4, v);
    } else {
        const int* idx; int valid; int off;
        if (w == 2)      { idx = pk; valid = vp[b]; off = 256; }
        else if (w == 3) { idx = tk; valid = vt[b]; off = 320; }
        else             { idx = ik; valid = vi[b]; off = 384; }
        // hoist indices: one coalesced load, broadcast via shfl (converged)
        int my_idx = (lane < KK) ? idx[b * KK + lane] : 0;
        int d = lane & 15, ko = lane >> 4;
        float4 acc = make_float4(0.f, 0.f, 0.f, 0.f);
        const int nIt = (valid + 1) >> 1;           // warp-uniform trip count
        for (int k2 = 0; k2 < nIt; k2++) {
            int k = k2 * 2 + ko;
            int r = __shfl_sync(0xffffffffu, my_idx, k < KK ? k : 0);
            if (k < valid) {
                float4 v = ((const float4*)(ek + (size_t)r * 64))[d];
                acc.x += v.x; acc.y += v.y; acc.z += v.z; acc.w += v.w;
            }
        }
        acc.x += __shfl_xor_sync(0xffffffffu, acc.x, 16);
        acc.y += __shfl_xor_sync(0xffffffffu, acc.y, 16);
        acc.z += __shfl_xor_sync(0xffffffffu, acc.z, 16);
        acc.w += __shfl_xor_sync(0xffffffffu, acc.w, 16);
        if (lane < 16) {
            float s = (valid > 0) ? (1.f / (float)valid) : 0.f;
            acc.x *= s; acc.y *= s; acc.z *= s; acc.w *= s;
            store4(Xh + off + d * 4, Xl + off + d * 4, acc);
        }
    }
}

// ---------------------------------------------------------------------------
// bf16x3 MMA core: CTA tile 128(M) x 128(N), K chunks of 32, double-buffered
// cp.async. 8 warps: wm = w&3 (M), wn = w>>2 (N). Warp tile 32x64.
// ---------------------------------------------------------------------------
template<int LDA, int LDB, int NC>
__device__ __forceinline__ void gemm_core(
    uint32_t sb,
    const __nv_bfloat16* __restrict__ Ahi, const __nv_bfloat16* __restrict__ Alo,
    const __nv_bfloat16* __restrict__ Bhi, const __nv_bfloat16* __restrict__ Blo,
    float acc[2][8][4])
{
    const int tid = threadIdx.x;
    const int lane = tid & 31, w = tid >> 5;
    const int wm = w & 3, wn = w >> 2;

    auto load_chunk = [&](int buf, int kc) {
        const uint32_t base = sb + buf * BUF_B;
        #pragma unroll
        for (int i = tid; i < 512; i += 256) {
            int row = i >> 2, seg = i & 3;
            uint32_t so = base + (uint32_t)(row * TROW + seg * 8) * 2;
            int go = kc * 32 + seg * 8;
            cpasync16(so,               Ahi + (size_t)row * LDA + go);
            cpasync16(so + PLANE_B,     Alo + (size_t)row * LDA + go);
            cpasync16(so + 2 * PLANE_B, Bhi + (size_t)row * LDB + go);
            cpasync16(so + 3 * PLANE_B, Blo + (size_t)row * LDB + go);
        }
        CP_COMMIT();
    };

    load_chunk(0, 0);

    for (int kc = 0; kc < NC; kc++) {
        if (kc + 1 < NC) { load_chunk((kc + 1) & 1, kc + 1); CP_WAIT(1); }
        else             { CP_WAIT(0); }
        __syncthreads();

        const uint32_t bA = sb + (kc & 1) * BUF_B;
        const uint32_t bB = bA + 2 * PLANE_B;
        #pragma unroll
        for (int ks = 0; ks < 2; ks++) {
            const int k0 = ks * 16;
            uint32_t aoff = (uint32_t)((wm * 32 + (lane & 15)) * TROW + k0 + (lane >> 4) * 8) * 2;
            uint32_t ah[2][4], al[2][4];
            ldsm4(ah[0], bA + aoff);
            ldsm4(ah[1], bA + aoff + 16 * TROW * 2);
            ldsm4(al[0], bA + PLANE_B + aoff);
            ldsm4(al[1], bA + PLANE_B + aoff + 16 * TROW * 2);

            const int q = lane >> 3;
            uint32_t brow0 = (uint32_t)(wn * 64 + (q >> 1) * 8 + (lane & 7));
            uint32_t bcol  = (uint32_t)(k0 + (q & 1) * 8);
            uint32_t bh[8][2], bl[8][2];
            #pragma unroll
            for (int p = 0; p < 4; p++) {
                uint32_t off = ((brow0 + p * 16) * TROW + bcol) * 2;
                uint32_t t[4];
                ldsm4(t, bB + off);
                bh[2*p][0] = t[0]; bh[2*p][1] = t[1];
                bh[2*p+1][0] = t[2]; bh[2*p+1][1] = t[3];
                ldsm4(t, bB + PLANE_B + off);
                bl[2*p][0] = t[0]; bl[2*p][1] = t[1];
                bl[2*p+1][0] = t[2]; bl[2*p+1][1] = t[3];
            }
            #pragma unroll
            for (int mt = 0; mt < 2; mt++)
                #pragma unroll
                for (int nt = 0; nt < 8; nt++) {
                    mma16816(acc[mt][nt], ah[mt], bh[nt]);
                    mma16816(acc[mt][nt], ah[mt], bl[nt]);
                    mma16816(acc[mt][nt], al[mt], bh[nt]);
                }
        }
        __syncthreads();
    }
}

// ---------------------------------------------------------------------------
// GEMM1: H1 = relu(X @ W1 + b1)   grid (512, 2)
// ---------------------------------------------------------------------------
__global__ __launch_bounds__(256, 2) void k_gemm1(const float* __restrict__ b1)
{
    extern __shared__ char smem[];
    const uint32_t sb = smem_u32(smem);
    const size_t rowBase = (size_t)blockIdx.x * 128;
    const int colBase = blockIdx.y * 128;

    float acc[2][8][4];
    #pragma unroll
    for (int a = 0; a < 2; a++)
        #pragma unroll
        for (int b = 0; b < 8; b++)
            #pragma unroll
            for (int c = 0; c < 4; c++) acc[a][b][c] = 0.f;

    gemm_core<448, 448, 14>(sb,
        g_Xhi + rowBase * 448, g_Xlo + rowBase * 448,
        g_W1Thi + (size_t)colBase * 448, g_W1Tlo + (size_t)colBase * 448, acc);

    const int tid = threadIdx.x, lane = tid & 31, w = tid >> 5;
    const int wm = w & 3, wn = w >> 2, grp = lane >> 2, tig = lane & 3;
    #pragma unroll
    for (int mt = 0; mt < 2; mt++) {
        const size_t r0 = rowBase + wm * 32 + mt * 16 + grp;
        #pragma unroll
        for (int nt = 0; nt < 8; nt++) {
            const int c = colBase + wn * 64 + nt * 8 + tig * 2;
            float bb0 = __ldg(b1 + c), bb1 = __ldg(b1 + c + 1);
            float v00 = fmaxf(acc[mt][nt][0] + bb0, 0.f);
            float v01 = fmaxf(acc[mt][nt][1] + bb1, 0.f);
            float v10 = fmaxf(acc[mt][nt][2] + bb0, 0.f);
            float v11 = fmaxf(acc[mt][nt][3] + bb1, 0.f);
            __nv_bfloat16 h0, l0, h1, l1;
            bf16split(v00, h0, l0); bf16split(v01, h1, l1);
            *(__nv_bfloat162*)(g_H1hi + r0 * 256 + c) = __nv_bfloat162(h0, h1);
            *(__nv_bfloat162*)(g_H1lo + r0 * 256 + c) = __nv_bfloat162(l0, l1);
            bf16split(v10, h0, l0); bf16split(v11, h1, l1);
            *(__nv_bfloat162*)(g_H1hi + (r0 + 8) * 256 + c) = __nv_bfloat162(h0, h1);
            *(__nv_bfloat162*)(g_H1lo + (r0 + 8) * 256 + c) = __nv_bfloat162(l0, l1);
        }
    }
}

// ---------------------------------------------------------------------------
// GEMM2 + MMA tail: h2 = relu(H1@W2+b2) -> smem bf16 planes;
// h3 = relu(h2@W3+b3) via bf16x3 HMMA (W3 frags direct from gmem/L1);
// out = h3@Wp + bp via reduction. smem ~82KB -> 2 CTAs/SM.
// ---------------------------------------------------------------------------
__global__ __launch_bounds__(256, 2) void k_gemm2_tail(
    const float* __restrict__ b2, const float* __restrict__ b3,
    const float* __restrict__ Wp, const float* __restrict__ bp,
    float* __restrict__ out)
{
    extern __shared__ char smem[];
    const uint32_t sb = smem_u32(smem);
    const int tid = threadIdx.x, lane = tid & 31, w = tid >> 5;
    const int wm = w & 3, wn = w >> 2, grp = lane >> 2, tig = lane & 3;
    const size_t rowBase = (size_t)blockIdx.x * 128;

    float acc[2][8][4];
    #pragma unroll
    for (int a = 0; a < 2; a++)
        #pragma unroll
        for (int b = 0; b < 8; b++)
            #pragma unroll
            for (int c = 0; c < 4; c++) acc[a][b][c] = 0.f;

    gemm_core<256, 256, 8>(sb,
        g_H1hi + rowBase * 256, g_H1lo + rowBase * 256,
        g_W2Thi, g_W2Tlo, acc);

    // h2 = relu(acc + b2) -> smem bf16 hi/lo planes (stride L3ROW), reusing pipe region
    __nv_bfloat16* h2hi = (__nv_bfloat16*)smem;
    __nv_bfloat16* h2lo = (__nv_bfloat16*)(smem + H2_PLANE);
    float* h3sum = (float*)(smem + G2_SUM);
    {
        #pragma unroll
        for (int mt = 0; mt < 2; mt++) {
            const int r = wm * 32 + mt * 16 + grp;
            #pragma unroll
            for (int nt = 0; nt < 8; nt++) {
                const int c = wn * 64 + nt * 8 + tig * 2;
                float bb0 = __ldg(b2 + c), bb1 = __ldg(b2 + c + 1);
                float v00 = fmaxf(acc[mt][nt][0] + bb0, 0.f);
                float v01 = fmaxf(acc[mt][nt][1] + bb1, 0.f);
                float v10 = fmaxf(acc[mt][nt][2] + bb0, 0.f);
                float v11 = fmaxf(acc[mt][nt][3] + bb1, 0.f);
                __nv_bfloat16 h0, l0, h1, l1;
                bf16split(v00, h0, l0); bf16split(v01, h1, l1);
                *(__nv_bfloat162*)(h2hi + r * L3ROW + c) = __nv_bfloat162(h0, h1);
                *(__nv_bfloat162*)(h2lo + r * L3ROW + c) = __nv_bfloat162(l0, l1);
                bf16split(v10, h0, l0); bf16split(v11, h1, l1);
                *(__nv_bfloat162*)(h2hi + (r + 8) * L3ROW + c) = __nv_bfloat162(h0, h1);
                *(__nv_bfloat162*)(h2lo + (r + 8) * L3ROW + c) = __nv_bfloat162(l0, l1);
            }
        }
    }
    if (tid < 128) h3sum[tid] = 0.f;
    __syncthreads();

    // layer 3 via bf16x3 HMMA: M=128, N=64 (wn covers 32 = 4 n-tiles), K=128.
    // A (h2) via ldmatrix from smem; B (W3T) fragments direct 4B loads (L1 broadcast):
    //   b0 = W3T[n][k0+tig*2 .. +1], b1 = +8   (n = lane>>2 = grp)
    float acc3[2][4][4];
    #pragma unroll
    for (int a = 0; a < 2; a++)
        #pragma unroll
        for (int b = 0; b < 4; b++)
            #pragma unroll
            for (int c = 0; c < 4; c++) acc3[a][b][c] = 0.f;

    const uint32_t hA = sb;
    #pragma unroll
    for (int kc = 0; kc < 8; kc++) {
        const int k0 = kc * 16;
        uint32_t aoff = (uint32_t)((wm * 32 + (lane & 15)) * L3ROW + k0 + (lane >> 4) * 8) * 2;
        uint32_t ah[2][4], al[2][4];
        ldsm4(ah[0], hA + aoff);
        ldsm4(ah[1], hA + aoff + 16 * L3ROW * 2);
        ldsm4(al[0], hA + H2_PLANE + aoff);
        ldsm4(al[1], hA + H2_PLANE + aoff + 16 * L3ROW * 2);

        uint32_t bh[4][2], bl[4][2];
        #pragma unroll
        for (int nt = 0; nt < 4; nt++) {
            const int n = wn * 32 + nt * 8 + grp;
            const int base = n * 128 + k0 + tig * 2;
            bh[nt][0] = *(const uint32_t*)(g_W3Thi + base);
            bh[nt][1] = *(const uint32_t*)(g_W3Thi + base + 8);
            bl[nt][0] = *(const uint32_t*)(g_W3Tlo + base);
            bl[nt][1] = *(const uint32_t*)(g_W3Tlo + base + 8);
        }
        #pragma unroll
        for (int mt = 0; mt < 2; mt++)
            #pragma unroll
            for (int nt = 0; nt < 4; nt++) {
                mma16816(acc3[mt][nt], ah[mt], bh[nt]);
                mma16816(acc3[mt][nt], ah[mt], bl[nt]);
                mma16816(acc3[mt][nt], al[mt], bh[nt]);
            }
    }

    // head: relu(h3 + b3) . Wp, reduce to per-row sums
    {
        float rs[2][2] = {{0.f, 0.f}, {0.f, 0.f}};
        #pragma unroll
        for (int nt = 0; nt < 4; nt++) {
            const int c = wn * 32 + nt * 8 + tig * 2;
            float bb0 = __ldg(b3 + c),  bb1 = __ldg(b3 + c + 1);
            float wp0 = __ldg(Wp + c),  wp1 = __ldg(Wp + c + 1);
            #pragma unroll
            for (int mt = 0; mt < 2; mt++) {
                rs[mt][0] += fmaxf(acc3[mt][nt][0] + bb0, 0.f) * wp0
                           + fmaxf(acc3[mt][nt][1] + bb1, 0.f) * wp1;
                rs[mt][1] += fmaxf(acc3[mt][nt][2] + bb0, 0.f) * wp0
                           + fmaxf(acc3[mt][nt][3] + bb1, 0.f) * wp1;
            }
        }
        #pragma unroll
        for (int mt = 0; mt < 2; mt++)
            #pragma unroll
            for (int h = 0; h < 2; h++) {
                rs[mt][h] += __shfl_xor_sync(0xffffffffu, rs[mt][h], 1);
                rs[mt][h] += __shfl_xor_sync(0xffffffffu, rs[mt][h], 2);
            }
        if (tig == 0) {
            #pragma unroll
            for (int mt = 0; mt < 2; mt++) {
                atomicAdd(&h3sum[wm * 32 + mt * 16 + grp],     rs[mt][0]);
                atomicAdd(&h3sum[wm * 32 + mt * 16 + grp + 8], rs[mt][1]);
            }
        }
    }
    __syncthreads();
    if (tid < 128) out[rowBase + tid] = h3sum[tid] + __ldg(bp);
}

// ---------------------------------------------------------------------------
extern "C" void kernel_launch(void* const* d_in, const int* in_sizes, int n_in,
                              void* d_out, int out_size)
{
    const int*   user = (const int*)d_in[0];
    const int*   item = (const int*)d_in[1];
    const int*   pk   = (const int*)d_in[2];
    const int*   tk   = (const int*)d_in[3];
    const int*   ik   = (const int*)d_in[4];
    const int*   vp   = (const int*)d_in[5];
    const int*   vt   = (const int*)d_in[6];
    const int*   vi   = (const int*)d_in[7];
    const float* eu   = (const float*)d_in[8];
    const float* ei   = (const float*)d_in[9];
    const float* ek   = (const float*)d_in[10];
    const float* W1   = (const float*)d_in[11];
    const float* b1   = (const float*)d_in[12];
    const float* W2   = (const float*)d_in[13];
    const float* b2   = (const float*)d_in[14];
    const float* W3   = (const float*)d_in[15];
    const float* b3   = (const float*)d_in[16];
    const float* Wp   = (const float*)d_in[17];
    const float* bp   = (const float*)d_in[18];
    float* out = (float*)d_out;

    cudaFuncSetAttribute(k_gemm1,      cudaFuncAttributeMaxDynamicSharedMemorySize, PIPE_B);
    cudaFuncSetAttribute(k_gemm2_tail, cudaFuncAttributeMaxDynamicSharedMemorySize, G2_BYTES);

    const int prep_n = 448 * 256 + 256 * 128 + 64 * 128;
    k_prep<<<(prep_n + 255) / 256, 256>>>(W1, W2, W3);
    k_assemble<<<NB, 160>>>(user, item, pk, tk, ik, vp, vt, vi, eu, ei, ek);
    k_gemm1<<<dim3(NB / 128, 2), 256, PIPE_B>>>(b1);
    k_gemm2_tail<<<NB / 128, 256, G2_BYTES>>>(b2, b3, Wp, bp, out);
}